// round 7
// baseline (speedup 1.0000x reference)
#include <cuda_runtime.h>
#include <cuda_fp16.h>
#include <math.h>
#include <stdint.h>

#define N_NODES 100000
#define N_EDGES 1600000
#define IN_F 64
#define HID_F 64
#define OUT_F 16

#define SCAN_B 1024
#define MAX_SCAN_BLKS 128

// ---- scratch (static __device__ globals) ----
__device__ __align__(16) int    g_cnt[N_NODES];     // in-degree (zeroed by last kernel)
__device__ __align__(16) int    g_row[N_NODES];     // CSR exclusive offsets (begin)
__device__ __align__(16) int    g_rank[N_EDGES];    // edge rank within dst bucket
__device__ __align__(16) int    g_blksum[MAX_SCAN_BLKS];
__device__ __align__(16) float  g_dis[N_NODES];     // rsqrt(deg+1)
__device__ __align__(16) int2   g_csr[N_EDGES];     // (src, bits(dis[src]))
__device__ __align__(16) __half g_h1[(size_t)N_NODES * HID_F];  // x@W1 (unscaled, fp16)
__device__ __align__(16) float  g_h2[(size_t)N_NODES * OUT_F];  // layer-2 messages (unscaled)

// inline dtype detect: int64 node ids < 2^31 have zero odd 32-bit words
__device__ __forceinline__ int edge_stride(const int* __restrict__ ei32, int E) {
    int is64 = 1;
    int n = E < 16 ? E : 16;
#pragma unroll
    for (int i = 0; i < 16; i++)
        if (i < n && ei32[2 * i + 1] != 0) is64 = 0;
    return is64 ? 2 : 1;
}

// ---------------------------------------------------------------------------
// GEMM1: h1 = x @ W1, fp16 out, unscaled. 128x64 block tile, 4x8 thread tile.
__global__ __launch_bounds__(256) void gemm1_kernel(
    const float* __restrict__ x, const float* __restrict__ W1, int N) {
    __shared__ float Wsh[IN_F][HID_F];   // 16KB
    __shared__ float Xsh[16][128];       // 8KB per k-chunk (transposed)

    int tid = threadIdx.x;
    int tx = tid & 7;
    int ty = tid >> 3;
    int nb = blockIdx.x * 128;

    for (int i = tid; i < 1024; i += 256) {
        int row = i >> 4, c4 = (i & 15) << 2;
        *reinterpret_cast<float4*>(&Wsh[row][c4]) =
            *reinterpret_cast<const float4*>(&W1[row * HID_F + c4]);
    }

    float acc[4][8];
#pragma unroll
    for (int i = 0; i < 4; i++)
#pragma unroll
        for (int j = 0; j < 8; j++) acc[i][j] = 0.0f;

    for (int kc = 0; kc < 4; kc++) {
        int k0 = kc * 16;
        __syncthreads();
        for (int i = tid; i < 512; i += 256) {
            int node = i >> 2, k4 = (i & 3) << 2;
            float4 v = make_float4(0.f, 0.f, 0.f, 0.f);
            int n = nb + node;
            if (n < N)
                v = *reinterpret_cast<const float4*>(&x[(size_t)n * IN_F + k0 + k4]);
            Xsh[k4 + 0][node] = v.x;
            Xsh[k4 + 1][node] = v.y;
            Xsh[k4 + 2][node] = v.z;
            Xsh[k4 + 3][node] = v.w;
        }
        __syncthreads();
#pragma unroll
        for (int k = 0; k < 16; k++) {
            float4 xv = *reinterpret_cast<const float4*>(&Xsh[k][ty * 4]);
            float4 wa = *reinterpret_cast<const float4*>(&Wsh[k0 + k][tx * 8]);
            float4 wb = *reinterpret_cast<const float4*>(&Wsh[k0 + k][tx * 8 + 4]);
            float xs[4] = {xv.x, xv.y, xv.z, xv.w};
#pragma unroll
            for (int i = 0; i < 4; i++) {
                acc[i][0] += xs[i] * wa.x;
                acc[i][1] += xs[i] * wa.y;
                acc[i][2] += xs[i] * wa.z;
                acc[i][3] += xs[i] * wa.w;
                acc[i][4] += xs[i] * wb.x;
                acc[i][5] += xs[i] * wb.y;
                acc[i][6] += xs[i] * wb.z;
                acc[i][7] += xs[i] * wb.w;
            }
        }
    }

#pragma unroll
    for (int i = 0; i < 4; i++) {
        int n = nb + ty * 4 + i;
        if (n >= N) continue;
        __align__(16) __half2 h[4];
#pragma unroll
        for (int p = 0; p < 4; p++)
            h[p] = __floats2half2_rn(acc[i][p * 2], acc[i][p * 2 + 1]);
        *reinterpret_cast<uint4*>(&g_h1[(size_t)n * HID_F + tx * 8]) =
            *reinterpret_cast<uint4*>(h);
    }
}

// degree histogram on dst; stores per-edge rank within its bucket
__global__ void build_hist_kernel(const int* __restrict__ ei32, int E) {
    int e = blockIdx.x * blockDim.x + threadIdx.x;
    if (e >= E) return;
    int stride = edge_stride(ei32, E);
    int dst = ei32[((size_t)E + e) * stride];
    g_rank[e] = atomicAdd(&g_cnt[dst], 1);
}

// per-block exclusive scan (warp-shuffle, 2 barriers)
__global__ __launch_bounds__(SCAN_B) void scan1_kernel(int N) {
    __shared__ int wsum[32];
    int i = blockIdx.x * SCAN_B + threadIdx.x;
    int v = (i < N) ? g_cnt[i] : 0;
    int lane = threadIdx.x & 31, wid = threadIdx.x >> 5;

    int s = v;
#pragma unroll
    for (int o = 1; o < 32; o *= 2) {
        int t = __shfl_up_sync(0xffffffffu, s, o);
        if (lane >= o) s += t;
    }
    if (lane == 31) wsum[wid] = s;
    __syncthreads();
    if (wid == 0) {
        int w = wsum[lane];
        int ws = w;
#pragma unroll
        for (int o = 1; o < 32; o *= 2) {
            int t = __shfl_up_sync(0xffffffffu, ws, o);
            if (lane >= o) ws += t;
        }
        wsum[lane] = ws - w;
        if (lane == 31) g_blksum[blockIdx.x] = ws;
    }
    __syncthreads();
    if (i < N) g_row[i] = wsum[wid] + s - v;       // exclusive
}

// fixup: warp 0 scans block sums (4/lane); final offsets + dis
__global__ void scan3_kernel(int N, int nblks) {
    __shared__ int excl[MAX_SCAN_BLKS];
    int lane = threadIdx.x & 31;
    if (threadIdx.x < 32) {
        int b4 = lane * 4;
        int v0 = (b4 + 0 < nblks) ? g_blksum[b4 + 0] : 0;
        int v1 = (b4 + 1 < nblks) ? g_blksum[b4 + 1] : 0;
        int v2 = (b4 + 2 < nblks) ? g_blksum[b4 + 2] : 0;
        int v3 = (b4 + 3 < nblks) ? g_blksum[b4 + 3] : 0;
        int s4 = v0 + v1 + v2 + v3;
        int ss = s4;
#pragma unroll
        for (int o = 1; o < 32; o *= 2) {
            int t = __shfl_up_sync(0xffffffffu, ss, o);
            if (lane >= o) ss += t;
        }
        int ex = ss - s4;
        excl[b4 + 0] = ex;
        excl[b4 + 1] = ex + v0;
        excl[b4 + 2] = ex + v0 + v1;
        excl[b4 + 3] = ex + v0 + v1 + v2;
    }
    __syncthreads();
    int i = blockIdx.x * blockDim.x + threadIdx.x;
    if (i >= N) return;
    g_row[i] += excl[i >> 10];
    g_dis[i] = rsqrtf((float)(g_cnt[i] + 1));
}

// bucket fill — atomic-free: pos = row[dst] + rank[e]
__global__ void fill_kernel(const int* __restrict__ ei32, int E) {
    int e = blockIdx.x * blockDim.x + threadIdx.x;
    if (e >= E) return;
    int stride = edge_stride(ei32, E);
    int src = ei32[(size_t)e * stride];
    int dst = ei32[((size_t)E + e) * stride];
    int pos = g_row[dst] + g_rank[e];
    g_csr[pos] = make_int2(src, __float_as_int(g_dis[src]));
}

// ---------------------------------------------------------------------------
// Fused gather1 + gemm2:
//   agg1[n] = dis[n] * ( dis[n]*h1[n] + sum_s dis[s]*h1[s] )   (in registers)
//   h2[n]   = relu(agg1[n] + b1) @ W2                          (unscaled)
// 8 threads/node, 8 feats each; reduce-scatter over the 8-lane group.
__global__ __launch_bounds__(256) void gather1_gemm2_kernel(
    const float* __restrict__ b1, const float* __restrict__ W2, int N) {
    __shared__ float Wsh[HID_F][OUT_F];   // 4KB
    __shared__ float bsh[HID_F];
    for (int i = threadIdx.x; i < HID_F * OUT_F; i += 256)
        Wsh[i >> 4][i & 15] = W2[i];
    if (threadIdx.x < HID_F) bsh[threadIdx.x] = b1[threadIdx.x];
    __syncthreads();

    int t = blockIdx.x * blockDim.x + threadIdx.x;
    int n = t >> 3;
    int c = t & 7;
    if (n >= N) return;

    unsigned lane = threadIdx.x & 31;
    unsigned gmask = 0xffu << (lane & ~7u);

    float dn = g_dis[n];
    int beg = g_row[n];
    int end = beg + g_cnt[n];

    float acc[8];
    {   // self term: dis[n] * h1[n]
        uint4 raw = *reinterpret_cast<const uint4*>(&g_h1[(size_t)n * HID_F + c * 8]);
        const __half2* hp = reinterpret_cast<const __half2*>(&raw);
#pragma unroll
        for (int p = 0; p < 4; p++) {
            float2 f = __half22float2(hp[p]);
            acc[p * 2 + 0] = dn * f.x;
            acc[p * 2 + 1] = dn * f.y;
        }
    }

    int j = beg;
    for (; j + 2 <= end; j += 2) {
        int2 ld = make_int2(0, 0);
        if (c < 2) ld = g_csr[j + c];
        int   s0 = __shfl_sync(gmask, ld.x, 0, 8);
        float d0 = __int_as_float(__shfl_sync(gmask, ld.y, 0, 8));
        int   s1 = __shfl_sync(gmask, ld.x, 1, 8);
        float d1 = __int_as_float(__shfl_sync(gmask, ld.y, 1, 8));

        uint4 ra = *reinterpret_cast<const uint4*>(&g_h1[(size_t)s0 * HID_F + c * 8]);
        uint4 rb = *reinterpret_cast<const uint4*>(&g_h1[(size_t)s1 * HID_F + c * 8]);
        const __half2* ha = reinterpret_cast<const __half2*>(&ra);
        const __half2* hb = reinterpret_cast<const __half2*>(&rb);
#pragma unroll
        for (int p = 0; p < 4; p++) {
            float2 fa = __half22float2(ha[p]);
            float2 fb = __half22float2(hb[p]);
            acc[p * 2 + 0] += d0 * fa.x + d1 * fb.x;
            acc[p * 2 + 1] += d0 * fa.y + d1 * fb.y;
        }
    }
    if (j < end) {
        int2 ld = make_int2(0, 0);
        if (c == 0) ld = g_csr[j];
        int   s0 = __shfl_sync(gmask, ld.x, 0, 8);
        float d0 = __int_as_float(__shfl_sync(gmask, ld.y, 0, 8));
        uint4 ra = *reinterpret_cast<const uint4*>(&g_h1[(size_t)s0 * HID_F + c * 8]);
        const __half2* ha = reinterpret_cast<const __half2*>(&ra);
#pragma unroll
        for (int p = 0; p < 4; p++) {
            float2 fa = __half22float2(ha[p]);
            acc[p * 2 + 0] += d0 * fa.x;
            acc[p * 2 + 1] += d0 * fa.y;
        }
    }

    // gemm2 partials: this lane covers k = c*8 .. c*8+7
    float out16[16];
#pragma unroll
    for (int o = 0; o < 16; o++) out16[o] = 0.0f;
#pragma unroll
    for (int kk = 0; kk < 8; kk++) {
        int k = c * 8 + kk;
        float h = fmaxf(acc[kk] * dn + bsh[k], 0.0f);
#pragma unroll
        for (int j4 = 0; j4 < 4; j4++) {
            float4 w = *reinterpret_cast<const float4*>(&Wsh[k][j4 * 4]);
            out16[j4 * 4 + 0] += h * w.x;
            out16[j4 * 4 + 1] += h * w.y;
            out16[j4 * 4 + 2] += h * w.z;
            out16[j4 * 4 + 3] += h * w.w;
        }
    }

    // reduce-scatter across 8 lanes: 16 -> 8 -> 4 -> 2 values/lane
    float v8[8];
    {
        int c0 = c & 1;
#pragma unroll
        for (int i = 0; i < 8; i++) {
            float keep = out16[c0 * 8 + i];
            float send = out16[(c0 ^ 1) * 8 + i];
            v8[i] = keep + __shfl_xor_sync(gmask, send, 1, 8);
        }
    }
    float v4[4];
    {
        int c1 = (c >> 1) & 1;
#pragma unroll
        for (int i = 0; i < 4; i++) {
            float keep = v8[c1 * 4 + i];
            float send = v8[(c1 ^ 1) * 4 + i];
            v4[i] = keep + __shfl_xor_sync(gmask, send, 2, 8);
        }
    }
    float v2[2];
    {
        int c2 = (c >> 2) & 1;
#pragma unroll
        for (int i = 0; i < 2; i++) {
            float keep = v4[c2 * 2 + i];
            float send = v4[(c2 ^ 1) * 2 + i];
            v2[i] = keep + __shfl_xor_sync(gmask, send, 4, 8);
        }
    }
    // lane c owns outputs j0, j0+1
    int j0 = ((c & 1) << 3) | ((c & 2) << 1) | ((c & 4) >> 1);
    *reinterpret_cast<float2*>(&g_h2[(size_t)n * OUT_F + j0]) =
        make_float2(v2[0], v2[1]);
}

// gather layer 2 + log_softmax fused. 4 threads/node. Re-zeroes g_cnt.
__global__ __launch_bounds__(256) void gather2_lsm_kernel(
    const float* __restrict__ b2, float* __restrict__ out, int N) {
    int t = blockIdx.x * blockDim.x + threadIdx.x;
    int n = t >> 2;
    int c = t & 3;
    if (n >= N) return;

    unsigned lane = threadIdx.x & 31;
    unsigned gmask = 0xfu << (lane & ~3u);

    float dn = g_dis[n];
    int beg = g_row[n];
    int end = beg + g_cnt[n];

    float4 self = *reinterpret_cast<const float4*>(&g_h2[(size_t)n * OUT_F + c * 4]);
    float acc[4] = {dn * self.x, dn * self.y, dn * self.z, dn * self.w};

    int j = beg;
    for (; j + 2 <= end; j += 2) {
        int2 ld = make_int2(0, 0);
        if (c < 2) ld = g_csr[j + c];
        int   s0 = __shfl_sync(gmask, ld.x, 0, 4);
        float d0 = __int_as_float(__shfl_sync(gmask, ld.y, 0, 4));
        int   s1 = __shfl_sync(gmask, ld.x, 1, 4);
        float d1 = __int_as_float(__shfl_sync(gmask, ld.y, 1, 4));
        float4 va = *reinterpret_cast<const float4*>(&g_h2[(size_t)s0 * OUT_F + c * 4]);
        float4 vb = *reinterpret_cast<const float4*>(&g_h2[(size_t)s1 * OUT_F + c * 4]);
        acc[0] += d0 * va.x + d1 * vb.x;
        acc[1] += d0 * va.y + d1 * vb.y;
        acc[2] += d0 * va.z + d1 * vb.z;
        acc[3] += d0 * va.w + d1 * vb.w;
    }
    if (j < end) {
        int2 ld = make_int2(0, 0);
        if (c == 0) ld = g_csr[j];
        int   s0 = __shfl_sync(gmask, ld.x, 0, 4);
        float d0 = __int_as_float(__shfl_sync(gmask, ld.y, 0, 4));
        float4 va = *reinterpret_cast<const float4*>(&g_h2[(size_t)s0 * OUT_F + c * 4]);
        acc[0] += d0 * va.x;
        acc[1] += d0 * va.y;
        acc[2] += d0 * va.z;
        acc[3] += d0 * va.w;
    }

    float4 bb = *reinterpret_cast<const float4*>(&b2[c * 4]);
    float v[4] = {acc[0] * dn + bb.x, acc[1] * dn + bb.y,
                  acc[2] * dn + bb.z, acc[3] * dn + bb.w};

    float mx = fmaxf(fmaxf(v[0], v[1]), fmaxf(v[2], v[3]));
    mx = fmaxf(mx, __shfl_xor_sync(gmask, mx, 1, 4));
    mx = fmaxf(mx, __shfl_xor_sync(gmask, mx, 2, 4));
    float s = __expf(v[0] - mx) + __expf(v[1] - mx) +
              __expf(v[2] - mx) + __expf(v[3] - mx);
    s += __shfl_xor_sync(gmask, s, 1, 4);
    s += __shfl_xor_sync(gmask, s, 2, 4);
    float ls = mx + logf(s);

    *reinterpret_cast<float4*>(&out[(size_t)n * OUT_F + c * 4]) =
        make_float4(v[0] - ls, v[1] - ls, v[2] - ls, v[3] - ls);

    if (c == 0) g_cnt[n] = 0;
}

// ---------------------------------------------------------------------------
extern "C" void kernel_launch(void* const* d_in, const int* in_sizes, int n_in,
                              void* d_out, int out_size) {
    const float* x    = (const float*)d_in[0];
    const int*   ei32 = (const int*)d_in[1];
    const float* W1   = (const float*)d_in[2];
    const float* b1   = (const float*)d_in[3];
    const float* W2   = (const float*)d_in[4];
    const float* b2   = (const float*)d_in[5];
    float* out = (float*)d_out;

    int N = in_sizes[0] / IN_F;
    int E = in_sizes[1] / 2;

    const int T = 256;
    int gE = (E + T - 1) / T;
    int gN = (N + T - 1) / T;
    int nScanBlks = (N + SCAN_B - 1) / SCAN_B;

    static cudaStream_t s_side = 0;
    static cudaEvent_t ev_fork = 0, ev_join = 0;
    static int s_init = 0;
    if (!s_init) {
        s_init = 1;
        if (cudaStreamCreateWithFlags(&s_side, cudaStreamNonBlocking) != cudaSuccess)
            s_side = 0;
        if (s_side) {
            if (cudaEventCreateWithFlags(&ev_fork, cudaEventDisableTiming) != cudaSuccess ||
                cudaEventCreateWithFlags(&ev_join, cudaEventDisableTiming) != cudaSuccess)
                s_side = 0;
        }
    }

    if (s_side) {
        cudaEventRecord(ev_fork, 0);
        cudaStreamWaitEvent(s_side, ev_fork, 0);

        build_hist_kernel<<<gE, T, 0, s_side>>>(ei32, E);     // 1
        scan1_kernel<<<nScanBlks, SCAN_B, 0, s_side>>>(N);    // 2
        scan3_kernel<<<gN, T, 0, s_side>>>(N, nScanBlks);     // 3
        fill_kernel<<<gE, T, 0, s_side>>>(ei32, E);           // 4

        gemm1_kernel<<<(N + 127) / 128, 256>>>(x, W1, N);     // 5 (main, concurrent)

        cudaEventRecord(ev_join, s_side);
        cudaStreamWaitEvent(0, ev_join, 0);
    } else {
        gemm1_kernel<<<(N + 127) / 128, 256>>>(x, W1, N);
        build_hist_kernel<<<gE, T>>>(ei32, E);
        scan1_kernel<<<nScanBlks, SCAN_B>>>(N);
        scan3_kernel<<<gN, T>>>(N, nScanBlks);
        fill_kernel<<<gE, T>>>(ei32, E);
    }

    gather1_gemm2_kernel<<<(N * 8 + T - 1) / T, T>>>(b1, W2, N);   // 6 <- profiled
    gather2_lsm_kernel<<<(N * 4 + T - 1) / T, T>>>(b2, out, N);    // 7
}

// round 8
// speedup vs baseline: 1.5637x; 1.5637x over previous
#include <cuda_runtime.h>
#include <cuda_fp16.h>
#include <math.h>
#include <stdint.h>

#define N_NODES 100000
#define N_EDGES 1600000
#define IN_F 64
#define HID_F 64
#define OUT_F 16

#define SCAN_B 1024
#define MAX_SCAN_BLKS 128

// ---- scratch (static __device__ globals) ----
__device__ __align__(16) int    g_cnt[N_NODES];     // in-degree (zeroed by last kernel)
__device__ __align__(16) int    g_row[N_NODES];     // CSR exclusive offsets (begin)
__device__ __align__(16) int    g_rank[N_EDGES];    // edge rank within dst bucket
__device__ __align__(16) int    g_blksum[MAX_SCAN_BLKS];
__device__ __align__(16) float  g_dis[N_NODES];     // rsqrt(deg+1)
__device__ __align__(16) int2   g_csr[N_EDGES];     // (src, bits(dis[src]))
__device__ __align__(16) __half g_h1[(size_t)N_NODES * HID_F];  // x@W1 (unscaled, fp16)
__device__ __align__(16) float  g_agg1[(size_t)N_NODES * HID_F];
__device__ __align__(16) float  g_h2[(size_t)N_NODES * OUT_F];  // layer-2 messages (unscaled)

// inline dtype detect: int64 node ids < 2^31 have zero odd 32-bit words
__device__ __forceinline__ int edge_stride(const int* __restrict__ ei32, int E) {
    int is64 = 1;
    int n = E < 16 ? E : 16;
#pragma unroll
    for (int i = 0; i < 16; i++)
        if (i < n && ei32[2 * i + 1] != 0) is64 = 0;
    return is64 ? 2 : 1;
}

// ---------------------------------------------------------------------------
// GEMM1: h1 = x @ W1, fp16 out, unscaled. 128x64 block tile, 4x8 thread tile.
__global__ __launch_bounds__(256) void gemm1_kernel(
    const float* __restrict__ x, const float* __restrict__ W1, int N) {
    __shared__ float Wsh[IN_F][HID_F];   // 16KB
    __shared__ float Xsh[16][128];       // 8KB per k-chunk (transposed)

    int tid = threadIdx.x;
    int tx = tid & 7;
    int ty = tid >> 3;
    int nb = blockIdx.x * 128;

    for (int i = tid; i < 1024; i += 256) {
        int row = i >> 4, c4 = (i & 15) << 2;
        *reinterpret_cast<float4*>(&Wsh[row][c4]) =
            *reinterpret_cast<const float4*>(&W1[row * HID_F + c4]);
    }

    float acc[4][8];
#pragma unroll
    for (int i = 0; i < 4; i++)
#pragma unroll
        for (int j = 0; j < 8; j++) acc[i][j] = 0.0f;

    for (int kc = 0; kc < 4; kc++) {
        int k0 = kc * 16;
        __syncthreads();
        for (int i = tid; i < 512; i += 256) {
            int node = i >> 2, k4 = (i & 3) << 2;
            float4 v = make_float4(0.f, 0.f, 0.f, 0.f);
            int n = nb + node;
            if (n < N)
                v = *reinterpret_cast<const float4*>(&x[(size_t)n * IN_F + k0 + k4]);
            Xsh[k4 + 0][node] = v.x;
            Xsh[k4 + 1][node] = v.y;
            Xsh[k4 + 2][node] = v.z;
            Xsh[k4 + 3][node] = v.w;
        }
        __syncthreads();
#pragma unroll
        for (int k = 0; k < 16; k++) {
            float4 xv = *reinterpret_cast<const float4*>(&Xsh[k][ty * 4]);
            float4 wa = *reinterpret_cast<const float4*>(&Wsh[k0 + k][tx * 8]);
            float4 wb = *reinterpret_cast<const float4*>(&Wsh[k0 + k][tx * 8 + 4]);
            float xs[4] = {xv.x, xv.y, xv.z, xv.w};
#pragma unroll
            for (int i = 0; i < 4; i++) {
                acc[i][0] += xs[i] * wa.x;
                acc[i][1] += xs[i] * wa.y;
                acc[i][2] += xs[i] * wa.z;
                acc[i][3] += xs[i] * wa.w;
                acc[i][4] += xs[i] * wb.x;
                acc[i][5] += xs[i] * wb.y;
                acc[i][6] += xs[i] * wb.z;
                acc[i][7] += xs[i] * wb.w;
            }
        }
    }

#pragma unroll
    for (int i = 0; i < 4; i++) {
        int n = nb + ty * 4 + i;
        if (n >= N) continue;
        __align__(16) __half2 h[4];
#pragma unroll
        for (int p = 0; p < 4; p++)
            h[p] = __floats2half2_rn(acc[i][p * 2], acc[i][p * 2 + 1]);
        *reinterpret_cast<uint4*>(&g_h1[(size_t)n * HID_F + tx * 8]) =
            *reinterpret_cast<uint4*>(h);
    }
}

// degree histogram on dst; stores per-edge rank within its bucket
__global__ void build_hist_kernel(const int* __restrict__ ei32, int E) {
    int e = blockIdx.x * blockDim.x + threadIdx.x;
    if (e >= E) return;
    int stride = edge_stride(ei32, E);
    int dst = ei32[((size_t)E + e) * stride];
    g_rank[e] = atomicAdd(&g_cnt[dst], 1);
}

// per-block exclusive scan (warp-shuffle, 2 barriers)
__global__ __launch_bounds__(SCAN_B) void scan1_kernel(int N) {
    __shared__ int wsum[32];
    int i = blockIdx.x * SCAN_B + threadIdx.x;
    int v = (i < N) ? g_cnt[i] : 0;
    int lane = threadIdx.x & 31, wid = threadIdx.x >> 5;

    int s = v;
#pragma unroll
    for (int o = 1; o < 32; o *= 2) {
        int t = __shfl_up_sync(0xffffffffu, s, o);
        if (lane >= o) s += t;
    }
    if (lane == 31) wsum[wid] = s;
    __syncthreads();
    if (wid == 0) {
        int w = wsum[lane];
        int ws = w;
#pragma unroll
        for (int o = 1; o < 32; o *= 2) {
            int t = __shfl_up_sync(0xffffffffu, ws, o);
            if (lane >= o) ws += t;
        }
        wsum[lane] = ws - w;
        if (lane == 31) g_blksum[blockIdx.x] = ws;
    }
    __syncthreads();
    if (i < N) g_row[i] = wsum[wid] + s - v;       // exclusive
}

// fixup: warp 0 scans block sums (4/lane); final offsets + dis
__global__ void scan3_kernel(int N, int nblks) {
    __shared__ int excl[MAX_SCAN_BLKS];
    int lane = threadIdx.x & 31;
    if (threadIdx.x < 32) {
        int b4 = lane * 4;
        int v0 = (b4 + 0 < nblks) ? g_blksum[b4 + 0] : 0;
        int v1 = (b4 + 1 < nblks) ? g_blksum[b4 + 1] : 0;
        int v2 = (b4 + 2 < nblks) ? g_blksum[b4 + 2] : 0;
        int v3 = (b4 + 3 < nblks) ? g_blksum[b4 + 3] : 0;
        int s4 = v0 + v1 + v2 + v3;
        int ss = s4;
#pragma unroll
        for (int o = 1; o < 32; o *= 2) {
            int t = __shfl_up_sync(0xffffffffu, ss, o);
            if (lane >= o) ss += t;
        }
        int ex = ss - s4;
        excl[b4 + 0] = ex;
        excl[b4 + 1] = ex + v0;
        excl[b4 + 2] = ex + v0 + v1;
        excl[b4 + 3] = ex + v0 + v1 + v2;
    }
    __syncthreads();
    int i = blockIdx.x * blockDim.x + threadIdx.x;
    if (i >= N) return;
    g_row[i] += excl[i >> 10];
    g_dis[i] = rsqrtf((float)(g_cnt[i] + 1));
}

// bucket fill — atomic-free: pos = row[dst] + rank[e]
__global__ void fill_kernel(const int* __restrict__ ei32, int E) {
    int e = blockIdx.x * blockDim.x + threadIdx.x;
    if (e >= E) return;
    int stride = edge_stride(ei32, E);
    int src = ei32[(size_t)e * stride];
    int dst = ei32[((size_t)E + e) * stride];
    int pos = g_row[dst] + g_rank[e];
    g_csr[pos] = make_int2(src, __float_as_int(g_dis[src]));
}

// ---------------------------------------------------------------------------
// gather layer 1: agg1[n] = dis[n] * ( dis[n]*h1[n] + sum_s dis[s]*h1[s] )
// 8 threads/node, 8 halves each; 4-edge unroll for MLP=4.
__global__ __launch_bounds__(256) void gather1_kernel(int N) {
    int t = blockIdx.x * blockDim.x + threadIdx.x;
    int n = t >> 3;
    int c = t & 7;
    if (n >= N) return;

    unsigned lane = threadIdx.x & 31;
    unsigned gmask = 0xffu << (lane & ~7u);

    float dn = g_dis[n];
    int beg = g_row[n];
    int end = beg + g_cnt[n];

    float acc[8];
    {   // self term: dis[n] * h1[n]
        uint4 raw = *reinterpret_cast<const uint4*>(&g_h1[(size_t)n * HID_F + c * 8]);
        const __half2* hp = reinterpret_cast<const __half2*>(&raw);
#pragma unroll
        for (int p = 0; p < 4; p++) {
            float2 f = __half22float2(hp[p]);
            acc[p * 2 + 0] = dn * f.x;
            acc[p * 2 + 1] = dn * f.y;
        }
    }

    int j = beg;
    for (; j + 4 <= end; j += 4) {
        int2 ld = make_int2(0, 0);
        if (c < 4) ld = g_csr[j + c];
        int   s0 = __shfl_sync(gmask, ld.x, 0, 8);
        float d0 = __int_as_float(__shfl_sync(gmask, ld.y, 0, 8));
        int   s1 = __shfl_sync(gmask, ld.x, 1, 8);
        float d1 = __int_as_float(__shfl_sync(gmask, ld.y, 1, 8));
        int   s2 = __shfl_sync(gmask, ld.x, 2, 8);
        float d2 = __int_as_float(__shfl_sync(gmask, ld.y, 2, 8));
        int   s3 = __shfl_sync(gmask, ld.x, 3, 8);
        float d3 = __int_as_float(__shfl_sync(gmask, ld.y, 3, 8));

        uint4 ra = *reinterpret_cast<const uint4*>(&g_h1[(size_t)s0 * HID_F + c * 8]);
        uint4 rb = *reinterpret_cast<const uint4*>(&g_h1[(size_t)s1 * HID_F + c * 8]);
        uint4 rc = *reinterpret_cast<const uint4*>(&g_h1[(size_t)s2 * HID_F + c * 8]);
        uint4 rd = *reinterpret_cast<const uint4*>(&g_h1[(size_t)s3 * HID_F + c * 8]);
        const __half2* ha = reinterpret_cast<const __half2*>(&ra);
        const __half2* hb = reinterpret_cast<const __half2*>(&rb);
        const __half2* hc = reinterpret_cast<const __half2*>(&rc);
        const __half2* hd = reinterpret_cast<const __half2*>(&rd);
#pragma unroll
        for (int p = 0; p < 4; p++) {
            float2 fa = __half22float2(ha[p]);
            float2 fb = __half22float2(hb[p]);
            float2 fc = __half22float2(hc[p]);
            float2 fd = __half22float2(hd[p]);
            acc[p * 2 + 0] += d0 * fa.x + d1 * fb.x + d2 * fc.x + d3 * fd.x;
            acc[p * 2 + 1] += d0 * fa.y + d1 * fb.y + d2 * fc.y + d3 * fd.y;
        }
    }
    for (; j < end; j++) {
        int2 ld = make_int2(0, 0);
        if (c == 0) ld = g_csr[j];
        int   s0 = __shfl_sync(gmask, ld.x, 0, 8);
        float d0 = __int_as_float(__shfl_sync(gmask, ld.y, 0, 8));
        uint4 ra = *reinterpret_cast<const uint4*>(&g_h1[(size_t)s0 * HID_F + c * 8]);
        const __half2* ha = reinterpret_cast<const __half2*>(&ra);
#pragma unroll
        for (int p = 0; p < 4; p++) {
            float2 fa = __half22float2(ha[p]);
            acc[p * 2 + 0] += d0 * fa.x;
            acc[p * 2 + 1] += d0 * fa.y;
        }
    }

    float4 o0 = make_float4(acc[0] * dn, acc[1] * dn, acc[2] * dn, acc[3] * dn);
    float4 o1 = make_float4(acc[4] * dn, acc[5] * dn, acc[6] * dn, acc[7] * dn);
    float* dst = &g_agg1[(size_t)n * HID_F + c * 8];
    *reinterpret_cast<float4*>(dst) = o0;
    *reinterpret_cast<float4*>(dst + 4) = o1;
}

// GEMM2: h2 = relu(agg1 + b1) @ W2, unscaled fp32. 2 nodes/thread.
// All lanes read the same Wsh[k] row per step -> smem broadcast, conflict-free.
__global__ __launch_bounds__(256) void gemm2_kernel(
    const float* __restrict__ W2, const float* __restrict__ b1, int N) {
    __shared__ float Wsh[HID_F][OUT_F];
    __shared__ float bsh[HID_F];
    for (int i = threadIdx.x; i < HID_F * OUT_F; i += blockDim.x)
        Wsh[i >> 4][i & 15] = W2[i];
    if (threadIdx.x < HID_F) bsh[threadIdx.x] = b1[threadIdx.x];
    __syncthreads();

    int t = blockIdx.x * blockDim.x + threadIdx.x;
    int n0 = t * 2, n1 = t * 2 + 1;
    if (n0 >= N) return;
    bool has1 = (n1 < N);

    float acc0[OUT_F], acc1[OUT_F];
#pragma unroll
    for (int j = 0; j < OUT_F; j++) { acc0[j] = 0.0f; acc1[j] = 0.0f; }

    const float4* a0 = reinterpret_cast<const float4*>(&g_agg1[(size_t)n0 * HID_F]);
    const float4* a1 = reinterpret_cast<const float4*>(&g_agg1[(size_t)n1 * HID_F]);

#pragma unroll 4
    for (int k4 = 0; k4 < HID_F / 4; k4++) {
        float4 v0 = a0[k4];
        float4 v1 = has1 ? a1[k4] : make_float4(0.f, 0.f, 0.f, 0.f);
        float h0s[4] = {v0.x, v0.y, v0.z, v0.w};
        float h1s[4] = {v1.x, v1.y, v1.z, v1.w};
#pragma unroll
        for (int kk = 0; kk < 4; kk++) {
            int k = k4 * 4 + kk;
            float bb = bsh[k];
            float h0 = fmaxf(h0s[kk] + bb, 0.0f);
            float h1 = fmaxf(h1s[kk] + bb, 0.0f);
#pragma unroll
            for (int j4 = 0; j4 < OUT_F / 4; j4++) {
                float4 w = *reinterpret_cast<const float4*>(&Wsh[k][j4 * 4]);
                acc0[j4 * 4 + 0] += h0 * w.x;  acc1[j4 * 4 + 0] += h1 * w.x;
                acc0[j4 * 4 + 1] += h0 * w.y;  acc1[j4 * 4 + 1] += h1 * w.y;
                acc0[j4 * 4 + 2] += h0 * w.z;  acc1[j4 * 4 + 2] += h1 * w.z;
                acc0[j4 * 4 + 3] += h0 * w.w;  acc1[j4 * 4 + 3] += h1 * w.w;
            }
        }
    }

    float4* o0 = reinterpret_cast<float4*>(&g_h2[(size_t)n0 * OUT_F]);
#pragma unroll
    for (int j4 = 0; j4 < OUT_F / 4; j4++)
        o0[j4] = make_float4(acc0[j4 * 4], acc0[j4 * 4 + 1],
                             acc0[j4 * 4 + 2], acc0[j4 * 4 + 3]);
    if (has1) {
        float4* o1 = reinterpret_cast<float4*>(&g_h2[(size_t)n1 * OUT_F]);
#pragma unroll
        for (int j4 = 0; j4 < OUT_F / 4; j4++)
            o1[j4] = make_float4(acc1[j4 * 4], acc1[j4 * 4 + 1],
                                 acc1[j4 * 4 + 2], acc1[j4 * 4 + 3]);
    }
}

// gather layer 2 + log_softmax fused. 4 threads/node. Re-zeroes g_cnt.
__global__ __launch_bounds__(256) void gather2_lsm_kernel(
    const float* __restrict__ b2, float* __restrict__ out, int N) {
    int t = blockIdx.x * blockDim.x + threadIdx.x;
    int n = t >> 2;
    int c = t & 3;
    if (n >= N) return;

    unsigned lane = threadIdx.x & 31;
    unsigned gmask = 0xfu << (lane & ~3u);

    float dn = g_dis[n];
    int beg = g_row[n];
    int end = beg + g_cnt[n];

    float4 self = *reinterpret_cast<const float4*>(&g_h2[(size_t)n * OUT_F + c * 4]);
    float acc[4] = {dn * self.x, dn * self.y, dn * self.z, dn * self.w};

    int j = beg;
    for (; j + 4 <= end; j += 4) {
        int2 ld = g_csr[j + c];
        int   s0 = __shfl_sync(gmask, ld.x, 0, 4);
        float d0 = __int_as_float(__shfl_sync(gmask, ld.y, 0, 4));
        int   s1 = __shfl_sync(gmask, ld.x, 1, 4);
        float d1 = __int_as_float(__shfl_sync(gmask, ld.y, 1, 4));
        int   s2 = __shfl_sync(gmask, ld.x, 2, 4);
        float d2 = __int_as_float(__shfl_sync(gmask, ld.y, 2, 4));
        int   s3 = __shfl_sync(gmask, ld.x, 3, 4);
        float d3 = __int_as_float(__shfl_sync(gmask, ld.y, 3, 4));
        float4 va = *reinterpret_cast<const float4*>(&g_h2[(size_t)s0 * OUT_F + c * 4]);
        float4 vb = *reinterpret_cast<const float4*>(&g_h2[(size_t)s1 * OUT_F + c * 4]);
        float4 vc = *reinterpret_cast<const float4*>(&g_h2[(size_t)s2 * OUT_F + c * 4]);
        float4 vd = *reinterpret_cast<const float4*>(&g_h2[(size_t)s3 * OUT_F + c * 4]);
        acc[0] += d0 * va.x + d1 * vb.x + d2 * vc.x + d3 * vd.x;
        acc[1] += d0 * va.y + d1 * vb.y + d2 * vc.y + d3 * vd.y;
        acc[2] += d0 * va.z + d1 * vb.z + d2 * vc.z + d3 * vd.z;
        acc[3] += d0 * va.w + d1 * vb.w + d2 * vc.w + d3 * vd.w;
    }
    for (; j < end; j++) {
        int2 ld = make_int2(0, 0);
        if (c == 0) ld = g_csr[j];
        int   s0 = __shfl_sync(gmask, ld.x, 0, 4);
        float d0 = __int_as_float(__shfl_sync(gmask, ld.y, 0, 4));
        float4 va = *reinterpret_cast<const float4*>(&g_h2[(size_t)s0 * OUT_F + c * 4]);
        acc[0] += d0 * va.x;
        acc[1] += d0 * va.y;
        acc[2] += d0 * va.z;
        acc[3] += d0 * va.w;
    }

    float4 bb = *reinterpret_cast<const float4*>(&b2[c * 4]);
    float v[4] = {acc[0] * dn + bb.x, acc[1] * dn + bb.y,
                  acc[2] * dn + bb.z, acc[3] * dn + bb.w};

    float mx = fmaxf(fmaxf(v[0], v[1]), fmaxf(v[2], v[3]));
    mx = fmaxf(mx, __shfl_xor_sync(gmask, mx, 1, 4));
    mx = fmaxf(mx, __shfl_xor_sync(gmask, mx, 2, 4));
    float s = __expf(v[0] - mx) + __expf(v[1] - mx) +
              __expf(v[2] - mx) + __expf(v[3] - mx);
    s += __shfl_xor_sync(gmask, s, 1, 4);
    s += __shfl_xor_sync(gmask, s, 2, 4);
    float ls = mx + logf(s);

    *reinterpret_cast<float4*>(&out[(size_t)n * OUT_F + c * 4]) =
        make_float4(v[0] - ls, v[1] - ls, v[2] - ls, v[3] - ls);

    if (c == 0) g_cnt[n] = 0;
}

// ---------------------------------------------------------------------------
extern "C" void kernel_launch(void* const* d_in, const int* in_sizes, int n_in,
                              void* d_out, int out_size) {
    const float* x    = (const float*)d_in[0];
    const int*   ei32 = (const int*)d_in[1];
    const float* W1   = (const float*)d_in[2];
    const float* b1   = (const float*)d_in[3];
    const float* W2   = (const float*)d_in[4];
    const float* b2   = (const float*)d_in[5];
    float* out = (float*)d_out;

    int N = in_sizes[0] / IN_F;
    int E = in_sizes[1] / 2;

    const int T = 256;
    int gE = (E + T - 1) / T;
    int gN = (N + T - 1) / T;
    int nScanBlks = (N + SCAN_B - 1) / SCAN_B;

    static cudaStream_t s_side = 0;
    static cudaEvent_t ev_fork = 0, ev_join = 0;
    static int s_init = 0;
    if (!s_init) {
        s_init = 1;
        if (cudaStreamCreateWithFlags(&s_side, cudaStreamNonBlocking) != cudaSuccess)
            s_side = 0;
        if (s_side) {
            if (cudaEventCreateWithFlags(&ev_fork, cudaEventDisableTiming) != cudaSuccess ||
                cudaEventCreateWithFlags(&ev_join, cudaEventDisableTiming) != cudaSuccess)
                s_side = 0;
        }
    }

    if (s_side) {
        cudaEventRecord(ev_fork, 0);
        cudaStreamWaitEvent(s_side, ev_fork, 0);

        build_hist_kernel<<<gE, T, 0, s_side>>>(ei32, E);     // 1
        scan1_kernel<<<nScanBlks, SCAN_B, 0, s_side>>>(N);    // 2
        scan3_kernel<<<gN, T, 0, s_side>>>(N, nScanBlks);     // 3
        fill_kernel<<<gE, T, 0, s_side>>>(ei32, E);           // 4

        gemm1_kernel<<<(N + 127) / 128, 256>>>(x, W1, N);     // 5 (main, concurrent)

        cudaEventRecord(ev_join, s_side);
        cudaStreamWaitEvent(0, ev_join, 0);
    } else {
        gemm1_kernel<<<(N + 127) / 128, 256>>>(x, W1, N);
        build_hist_kernel<<<gE, T>>>(ei32, E);
        scan1_kernel<<<nScanBlks, SCAN_B>>>(N);
        scan3_kernel<<<gN, T>>>(N, nScanBlks);
        fill_kernel<<<gE, T>>>(ei32, E);
    }

    gather1_kernel<<<(N * 8 + T - 1) / T, T>>>(N);                 // 6 <- profiled
    gemm2_kernel<<<((N + 1) / 2 + T - 1) / T, T>>>(W2, b1, N);     // 7
    gather2_lsm_kernel<<<(N * 4 + T - 1) / T, T>>>(b2, out, N);    // 8
}